// round 3
// baseline (speedup 1.0000x reference)
#include <cuda_runtime.h>
#include <math.h>

// Problem constants
#define CDIM 1024
#define NPIX 4096      // 64*64
#define TN_  3         // S_REF + 1
#define KSVD 500
#define SREF 2

// ---------------- scratch: one arena (no allocation) ----------------
// layout: [0, 3*1024*4096)            Xn  -> later holds fd (in-place debias+renorm)
//         [XN_ELEMS, +3*500*4096)     coef
#define XN_ELEMS   ((size_t)TN_ * CDIM * NPIX)
#define COEF_ELEMS ((size_t)TN_ * KSVD * NPIX)
__device__ float g_arena[XN_ELEMS + COEF_ELEMS];
__device__ float g_protos[SREF * CDIM];
__device__ float g_counts[SREF];
__device__ float g_proto[CDIM];
__device__ int   g_mask[SREF * NPIX];
__device__ unsigned long long g_part[SREF * NPIX];

// ---------------- column L2 normalize over channel dim ----------------
// layout: in[t][c][n], norm over c for each (t,n). in may equal out.
__global__ void norm_cols_kernel(const float* __restrict__ in, float* __restrict__ out) {
    int t = blockIdx.y;
    int n = blockIdx.x * blockDim.x + threadIdx.x;
    const float* p = in + (size_t)t * CDIM * NPIX + n;
    float ss = 0.f;
#pragma unroll 8
    for (int c = 0; c < CDIM; c++) {
        float v = p[(size_t)c * NPIX];
        ss += v * v;
    }
    float sc = 1.0f / fmaxf(sqrtf(ss), 1e-12f);
    float* q = out + (size_t)t * CDIM * NPIX + n;
#pragma unroll 8
    for (int c = 0; c < CDIM; c++) {
        q[(size_t)c * NPIX] = p[(size_t)c * NPIX] * sc;
    }
}

// ---------------- mask prep: dtype-sniff, counts, partmax init ----------------
__global__ void mask_prep_kernel(const void* __restrict__ mraw) {
    __shared__ int flag;
    __shared__ float sh0[256], sh1[256];
    int tid = threadIdx.x;
    if (tid == 0) flag = 0;
    __syncthreads();
    const unsigned char* b = (const unsigned char*)mraw;
    // If the buffer is int32 0/1, every byte at offset %4 != 0 is zero.
    int local = 0;
    for (int i = tid; i < SREF * NPIX; i += blockDim.x) {
        if ((i & 3) != 0 && b[i] != 0) local = 1;
    }
    if (local) atomicOr(&flag, 1);
    __syncthreads();
    int isbyte = flag;
    float c0 = 0.f, c1 = 0.f;
    for (int i = tid; i < SREF * NPIX; i += blockDim.x) {
        int v = isbyte ? (int)b[i] : ((const int*)mraw)[i];
        int m = (v != 0) ? 1 : 0;
        g_mask[i] = m;
        if (i < NPIX) c0 += (float)m; else c1 += (float)m;
        g_part[i] = 0ull;
    }
    sh0[tid] = c0; sh1[tid] = c1;
    __syncthreads();
    for (int s = 128; s > 0; s >>= 1) {
        if (tid < s) { sh0[tid] += sh0[tid + s]; sh1[tid] += sh1[tid + s]; }
        __syncthreads();
    }
    if (tid == 0) { g_counts[0] = sh0[0]; g_counts[1] = sh1[0]; }
}

// ---------------- generic fp32 SGEMM: Out = (SUB_C ? Csub - A*B : A*B) ----------------
// A element (k,m): TRANS_A ? A[k*lda+m] : A[m*lda+k].  B is B[k*N+n], ldb=N.
// BM=BN=128, BK=8, 256 threads, 8x8 per-thread tile.
// NOTE: Out == Csub aliasing is safe: each block reads its Csub tile only in
// its own epilogue, immediately before writing the same addresses.
template <bool TRANS_A, bool SUB_C>
__global__ void sgemm_kernel(const float* __restrict__ A, const float* __restrict__ B,
                             const float* __restrict__ Csub, float* __restrict__ Out,
                             int M, int N, int K, int lda,
                             size_t sA, size_t sB, size_t sC, size_t sO) {
    A += (size_t)blockIdx.z * sA;
    B += (size_t)blockIdx.z * sB;
    Out += (size_t)blockIdx.z * sO;
    if (SUB_C) Csub += (size_t)blockIdx.z * sC;

    const int m0 = blockIdx.y * 128;
    const int n0 = blockIdx.x * 128;

    __shared__ float As[8][128];
    __shared__ float Bs[8][128];

    int tid = threadIdx.x;
    int tx = tid & 15;   // column group
    int ty = tid >> 4;   // row group

    float acc[8][8];
#pragma unroll
    for (int i = 0; i < 8; i++)
#pragma unroll
        for (int j = 0; j < 8; j++) acc[i][j] = 0.f;

    for (int k0 = 0; k0 < K; k0 += 8) {
        // load A tile -> As[kk][mm]
#pragma unroll
        for (int l = 0; l < 4; l++) {
            int e = tid + l * 256;
            if (TRANS_A) {
                int mm = e & 127, kk = e >> 7;
                int gm = m0 + mm, gk = k0 + kk;
                float v = 0.f;
                if (gk < K && gm < M) v = A[(size_t)gk * lda + gm];
                As[kk][mm] = v;
            } else {
                int kk = e & 7, mm = e >> 3;
                int gm = m0 + mm, gk = k0 + kk;
                float v = 0.f;
                if (gk < K && gm < M) v = A[(size_t)gm * lda + gk];
                As[kk][mm] = v;
            }
        }
        // load B tile -> Bs[kk][nn]  (N is always a multiple of 128 here)
#pragma unroll
        for (int l = 0; l < 4; l++) {
            int e = tid + l * 256;
            int nn = e & 127, kk = e >> 7;
            int gk = k0 + kk;
            Bs[kk][nn] = (gk < K) ? B[(size_t)gk * N + (n0 + nn)] : 0.f;
        }
        __syncthreads();

#pragma unroll
        for (int kk = 0; kk < 8; kk++) {
            float4 a0 = *(const float4*)&As[kk][ty * 8];
            float4 a1 = *(const float4*)&As[kk][ty * 8 + 4];
            float4 b0 = *(const float4*)&Bs[kk][tx * 8];
            float4 b1 = *(const float4*)&Bs[kk][tx * 8 + 4];
            float a[8] = {a0.x, a0.y, a0.z, a0.w, a1.x, a1.y, a1.z, a1.w};
            float b[8] = {b0.x, b0.y, b0.z, b0.w, b1.x, b1.y, b1.z, b1.w};
#pragma unroll
            for (int i = 0; i < 8; i++)
#pragma unroll
                for (int j = 0; j < 8; j++) acc[i][j] += a[i] * b[j];
        }
        __syncthreads();
    }

#pragma unroll
    for (int i = 0; i < 8; i++) {
        int gm = m0 + ty * 8 + i;
        if (gm < M) {
#pragma unroll
            for (int j = 0; j < 8; j++) {
                int gn = n0 + tx * 8 + j;
                float r = acc[i][j];
                if (SUB_C) r = Csub[(size_t)gm * N + gn] - r;
                Out[(size_t)gm * N + gn] = r;
            }
        }
    }
}

// ---------------- masked prototypes: protos[s][c] = sum_n fd[s][c][n]*mask ----------------
__global__ void protos_kernel() {
    int c = blockIdx.x;
    int s = blockIdx.y;
    int tid = threadIdx.x;
    const float* row = g_arena + (size_t)s * CDIM * NPIX + (size_t)c * NPIX;  // fd
    const int* m = g_mask + s * NPIX;
    float sum = 0.f;
    for (int n = tid; n < NPIX; n += 256) sum += m[n] ? row[n] : 0.f;
    __shared__ float sh[256];
    sh[tid] = sum;
    __syncthreads();
    for (int st = 128; st > 0; st >>= 1) {
        if (tid < st) sh[tid] += sh[tid + st];
        __syncthreads();
    }
    if (tid == 0) g_protos[s * CDIM + c] = sh[0];
}

// ---------------- ref_prototype = l2norm(mean_s(protos/count)) ----------------
// 256 threads, each owns 4 channels.
__global__ void proto_kernel() {
    __shared__ float sh[256];
    int tid = threadIdx.x;
    float c0 = fmaxf(g_counts[0], 1.f);
    float c1 = fmaxf(g_counts[1], 1.f);
    float p[4];
    float ss = 0.f;
#pragma unroll
    for (int i = 0; i < 4; i++) {
        int c = tid * 4 + i;
        p[i] = 0.5f * (g_protos[c] / c0 + g_protos[CDIM + c] / c1);
        ss += p[i] * p[i];
    }
    sh[tid] = ss;
    __syncthreads();
    for (int st = 128; st > 0; st >>= 1) {
        if (tid < st) sh[tid] += sh[tid + st];
        __syncthreads();
    }
    float sc = 1.0f / fmaxf(sqrtf(sh[0]), 1e-12f);
#pragma unroll
    for (int i = 0; i < 4; i++) g_proto[tid * 4 + i] = p[i] * sc;
}

// ---------------- sim_fwd[xy] = sum_c fd_tgt[c][xy] * proto[c] ----------------
__global__ void simfwd_kernel(float* __restrict__ out) {
    int xy = blockIdx.x * blockDim.x + threadIdx.x;
    const float* tgt = g_arena + (size_t)2 * CDIM * NPIX;  // fd[2]
    float acc = 0.f;
#pragma unroll 8
    for (int c = 0; c < CDIM; c++) acc += tgt[(size_t)c * NPIX + xy] * g_proto[c];
    out[xy] = acc;
}

// ---------------- argmax over hw for each (s, xy): partial pass ----------------
__global__ void argmax_part_kernel(const float* __restrict__ sim) {
    int s = blockIdx.z;
    int xy = blockIdx.x * 256 + threadIdx.x;
    int hw0 = blockIdx.y * 256;
    const float* base = sim + (size_t)s * NPIX * NPIX + xy;
    float best = -1e30f;
    int bi = hw0;
#pragma unroll 4
    for (int i = 0; i < 256; i++) {
        float v = base[(size_t)(hw0 + i) * NPIX];
        if (v > best) { best = v; bi = hw0 + i; }   // strict > keeps first max
    }
    unsigned int key = __float_as_uint(best);
    key = (key & 0x80000000u) ? ~key : (key | 0x80000000u);  // order-preserving
    // low word = ~hw so ties pick the SMALLEST hw (jnp.argmax semantics)
    unsigned long long pk = ((unsigned long long)key << 32) | (unsigned int)(0xFFFFFFFFu - (unsigned)bi);
    atomicMax(&g_part[s * NPIX + xy], pk);
}

__global__ void votes_kernel(float* __restrict__ out) {
    int xy = blockIdx.x * blockDim.x + threadIdx.x;
    int v = 0;
#pragma unroll
    for (int s = 0; s < SREF; s++) {
        unsigned long long pk = g_part[s * NPIX + xy];
        int hw = (int)(0xFFFFFFFFu - (unsigned int)(pk & 0xFFFFFFFFu));
        v += g_mask[s * NPIX + hw];
    }
    out[xy] = (float)v;
}

// ---------------- launch ----------------
extern "C" void kernel_launch(void* const* d_in, const int* in_sizes, int n_in,
                              void* d_out, int out_size) {
    const float* fmaps = (const float*)d_in[0];
    const void*  masks = d_in[1];
    const float* basis = (const float*)d_in[2];
    float* out = (float*)d_out;

    float* sim    = out;                                   // 2*4096*4096
    float* simfwd = out + (size_t)SREF * NPIX * NPIX;      // 4096
    float* votes  = simfwd + NPIX;                         // 4096

    float* arena = nullptr;
    cudaGetSymbolAddress((void**)&arena, g_arena);
    float* Xn   = arena;             // becomes fd in place after steps 3+4
    float* coef = arena + XN_ELEMS;

    // 1. normalize fmaps over channels -> Xn
    norm_cols_kernel<<<dim3(NPIX / 256, TN_), 256>>>(fmaps, Xn);

    // 2. coef[t] = basis^T * Xn[t]   (M=500, N=4096, K=1024), A = basis (TRANS_A, lda=500)
    sgemm_kernel<true, false><<<dim3(32, (KSVD + 127) / 128, TN_), 256>>>(
        basis, Xn, nullptr, coef,
        KSVD, NPIX, CDIM, KSVD,
        0, (size_t)CDIM * NPIX, 0, (size_t)KSVD * NPIX);

    // 3. Xn[t] <- Xn[t] - basis * coef[t]  IN PLACE  (M=1024, N=4096, K=500)
    sgemm_kernel<false, true><<<dim3(32, CDIM / 128, TN_), 256>>>(
        basis, coef, Xn, Xn,
        CDIM, NPIX, KSVD, KSVD,
        0, (size_t)KSVD * NPIX, (size_t)CDIM * NPIX, (size_t)CDIM * NPIX);

    // 4. normalize in place -> fd (lives in Xn)
    norm_cols_kernel<<<dim3(NPIX / 256, TN_), 256>>>(Xn, Xn);

    // 5. mask prep (dtype sniff + counts + partmax init)
    mask_prep_kernel<<<1, 256>>>(masks);

    // 6. prototypes
    protos_kernel<<<dim3(CDIM, SREF), 256>>>();
    proto_kernel<<<1, 256>>>();

    // 7. sim_fwd
    simfwd_kernel<<<NPIX / 256, 256>>>(simfwd);

    // 8. sim[s] = fd_ref[s]^T * fd_tgt  (M=4096, N=4096, K=1024), A = fd[s] (TRANS_A, lda=4096)
    sgemm_kernel<true, false><<<dim3(32, 32, SREF), 256>>>(
        Xn, Xn + (size_t)2 * CDIM * NPIX, nullptr, sim,
        NPIX, NPIX, CDIM, NPIX,
        (size_t)CDIM * NPIX, 0, 0, (size_t)NPIX * NPIX);

    // 9. argmax + votes
    argmax_part_kernel<<<dim3(16, 16, SREF), 256>>>(sim);
    votes_kernel<<<NPIX / 256, 256>>>(votes);
}